// round 10
// baseline (speedup 1.0000x reference)
#include <cuda_runtime.h>
#include <math.h>

#define VOCAB   50257
#define DIM     512
#define MAXDEP  20
#define NTOK    8192            // B*S
#define WPB     4               // warps (tokens) per 128-thread block
#define NBLOCK  (NTOK / WPB)    // 2048 blocks

__device__ float        g_partials[NBLOCK];
__device__ unsigned int g_count = 0;   // self-resets -> graph-replay safe

__global__ void __launch_bounds__(128) hs_kernel(
    const float* __restrict__ hidden,      // [NTOK, DIM]
    const float* __restrict__ node_emb,    // [VOCAB-1, DIM]
    const float* __restrict__ path_signs,  // [VOCAB, MAXDEP]
    const int*   __restrict__ targets,     // [NTOK]
    const int*   __restrict__ path_nodes,  // [VOCAB, MAXDEP]
    const int*   __restrict__ path_lens,   // [VOCAB]
    float*       __restrict__ out)
{
    __shared__ float s_warp[WPB];

    const int warp = threadIdx.x >> 5;
    const int lane = threadIdx.x & 31;
    const int tok  = blockIdx.x * WPB + warp;

    const int t   = targets[tok];
    int       len = path_lens[t];
    if (len < 1) len = 1;

    // Coalesced preload of path metadata; broadcast via shfl at use sites.
    int   my_node = 0;
    float my_sign = 1.0f;
    if (lane < MAXDEP) {
        my_node = path_nodes[(size_t)t * MAXDEP + lane];
        my_sign = (path_signs[(size_t)t * MAXDEP + lane] >= 0.0f) ? 1.0f : -1.0f;
    }

    // Hidden row: 16 floats/lane in registers.
    const float4* h4 = reinterpret_cast<const float4*>(hidden + (size_t)tok * DIM);
    const float4 h0 = h4[lane];
    const float4 h1 = h4[lane + 32];
    const float4 h2 = h4[lane + 64];
    const float4 h3 = h4[lane + 96];

    // ---- Prologue: rows 0 and 1 in flight (explicit named buffers).
    float4 c0, c1, c2, c3;    // row d   (compute)
    float4 n0, n1, n2, n3;    // row d+1 (in flight)
    {
        const int node = __shfl_sync(0xffffffffu, my_node, 0);
        const float4* w4 = reinterpret_cast<const float4*>(node_emb + (size_t)node * DIM);
        c0 = w4[lane]; c1 = w4[lane + 32]; c2 = w4[lane + 64]; c3 = w4[lane + 96];
    }
    {
        const int d1   = (1 < len) ? 1 : (len - 1);
        const int node = __shfl_sync(0xffffffffu, my_node, d1);
        const float4* w4 = reinterpret_cast<const float4*>(node_emb + (size_t)node * DIM);
        n0 = w4[lane]; n1 = w4[lane + 32]; n2 = w4[lane + 64]; n3 = w4[lane + 96];
    }

    float nll = 0.0f;

    // ---- 3-deep software pipeline (dynamic loop + explicit rotation,
    //      the form ptxas demonstrably keeps in flight).
    for (int d = 0; d < len; ++d) {
        // Prefetch row d+2 into the m-buffer (clamped -> L1-hot past the end).
        const int dn   = (d + 2 < len) ? (d + 2) : (len - 1);
        const int node = __shfl_sync(0xffffffffu, my_node, dn);
        const float4* w4 =
            reinterpret_cast<const float4*>(node_emb + (size_t)node * DIM);
        const float4 m0 = w4[lane];
        const float4 m1 = w4[lane + 32];
        const float4 m2 = w4[lane + 64];
        const float4 m3 = w4[lane + 96];

        // Compute with row d: issued two iterations ago -> data already resident.
        float a;
        a = h0.x * c0.x;           a = fmaf(h0.y, c0.y, a);
        a = fmaf(h0.z, c0.z, a);   a = fmaf(h0.w, c0.w, a);
        a = fmaf(h1.x, c1.x, a);   a = fmaf(h1.y, c1.y, a);
        a = fmaf(h1.z, c1.z, a);   a = fmaf(h1.w, c1.w, a);
        a = fmaf(h2.x, c2.x, a);   a = fmaf(h2.y, c2.y, a);
        a = fmaf(h2.z, c2.z, a);   a = fmaf(h2.w, c2.w, a);
        a = fmaf(h3.x, c3.x, a);   a = fmaf(h3.y, c3.y, a);
        a = fmaf(h3.z, c3.z, a);   a = fmaf(h3.w, c3.w, a);

        #pragma unroll
        for (int off = 16; off > 0; off >>= 1)
            a += __shfl_xor_sync(0xffffffffu, a, off);

        const float sgn = __shfl_sync(0xffffffffu, my_sign, d);
        const float z   = sgn * a;
        // -log sigmoid(z) = max(-z,0) + log1p(exp(-|z|))   (stable)
        nll += fmaxf(-z, 0.0f) + log1pf(expf(-fabsf(z)));

        // Rotate: c <- n (d+1 row, mostly landed), n <- m (just issued).
        c0 = n0; c1 = n1; c2 = n2; c3 = n3;
        n0 = m0; n1 = m1; n2 = m2; n3 = m3;
    }

    if (lane == 0) s_warp[warp] = nll;
    __syncthreads();

    if (threadIdx.x == 0) {
        float bs = 0.0f;
        #pragma unroll
        for (int i = 0; i < WPB; ++i) bs += s_warp[i];
        g_partials[blockIdx.x] = bs;
    }
    __threadfence();

    // Last-block-done: one block deterministically reduces all partials.
    __shared__ unsigned int s_last;
    if (threadIdx.x == 0)
        s_last = (atomicAdd(&g_count, 1u) == (unsigned)(gridDim.x - 1));
    __syncthreads();

    if (s_last) {
        float s = 0.0f;
        #pragma unroll
        for (int i = 0; i < NBLOCK / 128; ++i)
            s += g_partials[threadIdx.x + i * 128];

        __shared__ float sm[128];
        sm[threadIdx.x] = s;
        __syncthreads();
        #pragma unroll
        for (int k = 64; k > 0; k >>= 1) {
            if (threadIdx.x < k) sm[threadIdx.x] += sm[threadIdx.x + k];
            __syncthreads();
        }
        if (threadIdx.x == 0) {
            out[0]  = sm[0] * (1.0f / (float)NTOK);
            g_count = 0;   // reset for next launch / graph replay
        }
    }
}

extern "C" void kernel_launch(void* const* d_in, const int* in_sizes, int n_in,
                              void* d_out, int out_size)
{
    const float* hidden     = (const float*)d_in[0];
    const float* node_emb   = (const float*)d_in[1];
    const float* path_signs = (const float*)d_in[2];
    const int*   targets    = (const int*)  d_in[3];
    const int*   path_nodes = (const int*)  d_in[4];
    const int*   path_lens  = (const int*)  d_in[5];
    float*       out        = (float*)d_out;

    hs_kernel<<<NBLOCK, 128>>>(hidden, node_emb, path_signs,
                               targets, path_nodes, path_lens, out);
}

// round 12
// speedup vs baseline: 1.1322x; 1.1322x over previous
#include <cuda_runtime.h>
#include <math.h>

#define VOCAB   50257
#define DIM     512
#define MAXDEP  20
#define NTOK    8192            // B*S
#define WPB     4               // warps (tokens) per 128-thread block
#define NBLOCK  (NTOK / WPB)    // 2048 blocks

__device__ float        g_partials[NBLOCK];
__device__ unsigned int g_count = 0;   // self-resets -> graph-replay safe

__global__ void __launch_bounds__(128) hs_kernel(
    const float* __restrict__ hidden,      // [NTOK, DIM]
    const float* __restrict__ node_emb,    // [VOCAB-1, DIM]
    const float* __restrict__ path_signs,  // [VOCAB, MAXDEP]
    const int*   __restrict__ targets,     // [NTOK]
    const int*   __restrict__ path_nodes,  // [VOCAB, MAXDEP]
    const int*   __restrict__ path_lens,   // [VOCAB]
    float*       __restrict__ out)
{
    __shared__ float s_warp[WPB];

    const int warp = threadIdx.x >> 5;
    const int lane = threadIdx.x & 31;
    const int tok  = blockIdx.x * WPB + warp;

    const int t   = targets[tok];
    int       len = path_lens[t];
    if (len < 1) len = 1;

    // Coalesced preload of path metadata; broadcast via shfl at use sites.
    int   my_node = 0;
    float my_sign = 1.0f;
    if (lane < MAXDEP) {
        my_node = path_nodes[(size_t)t * MAXDEP + lane];
        my_sign = (path_signs[(size_t)t * MAXDEP + lane] >= 0.0f) ? 1.0f : -1.0f;
    }

    // Hidden row: 16 floats/lane in registers.
    const float4* h4 = reinterpret_cast<const float4*>(hidden + (size_t)tok * DIM);
    const float4 h0 = h4[lane];
    const float4 h1 = h4[lane + 32];
    const float4 h2 = h4[lane + 64];
    const float4 h3 = h4[lane + 96];

    // ---- Prologue: load row 0; L2-prefetch row 1 (full 2KB via per-lane lines).
    float4 c0, c1, c2, c3;
    {
        const int node = __shfl_sync(0xffffffffu, my_node, 0);
        const float4* w4 =
            reinterpret_cast<const float4*>(node_emb + (size_t)node * DIM);
        c0 = w4[lane]; c1 = w4[lane + 32]; c2 = w4[lane + 64]; c3 = w4[lane + 96];
    }
    if (1 < len) {
        const int node = __shfl_sync(0xffffffffu, my_node, 1);
        const char* row = reinterpret_cast<const char*>(node_emb + (size_t)node * DIM);
        asm volatile("prefetch.global.L2 [%0];" :: "l"(row + (lane & 15) * 128));
    }

    float nll = 0.0f;

    // ---- 2-deep register pipeline (R7-proven) + distance-2 L2 prefetch.
    for (int d = 0; d < len; ++d) {
        // L2-prefetch row d+2: no register cost, no scoreboard dependency.
        {
            const int dp   = (d + 2 < len) ? (d + 2) : (len - 1);
            const int node = __shfl_sync(0xffffffffu, my_node, dp);
            const char* row =
                reinterpret_cast<const char*>(node_emb + (size_t)node * DIM);
            asm volatile("prefetch.global.L2 [%0];" :: "l"(row + (lane & 15) * 128));
        }

        // Register prefetch of row d+1 (clamped -> L1-hot on last iteration).
        const int dn   = (d + 1 < len) ? (d + 1) : (len - 1);
        const int node = __shfl_sync(0xffffffffu, my_node, dn);
        const float4* w4 =
            reinterpret_cast<const float4*>(node_emb + (size_t)node * DIM);
        const float4 n0 = w4[lane];
        const float4 n1 = w4[lane + 32];
        const float4 n2 = w4[lane + 64];
        const float4 n3 = w4[lane + 96];

        // Compute with current buffer while the 4 prefetch LDG.128 are in flight.
        float a;
        a = h0.x * c0.x;           a = fmaf(h0.y, c0.y, a);
        a = fmaf(h0.z, c0.z, a);   a = fmaf(h0.w, c0.w, a);
        a = fmaf(h1.x, c1.x, a);   a = fmaf(h1.y, c1.y, a);
        a = fmaf(h1.z, c1.z, a);   a = fmaf(h1.w, c1.w, a);
        a = fmaf(h2.x, c2.x, a);   a = fmaf(h2.y, c2.y, a);
        a = fmaf(h2.z, c2.z, a);   a = fmaf(h2.w, c2.w, a);
        a = fmaf(h3.x, c3.x, a);   a = fmaf(h3.y, c3.y, a);
        a = fmaf(h3.z, c3.z, a);   a = fmaf(h3.w, c3.w, a);

        #pragma unroll
        for (int off = 16; off > 0; off >>= 1)
            a += __shfl_xor_sync(0xffffffffu, a, off);

        const float sgn = __shfl_sync(0xffffffffu, my_sign, d);
        const float z   = sgn * a;
        // -log sigmoid(z) = max(-z,0) + log1p(exp(-|z|))   (stable)
        nll += fmaxf(-z, 0.0f) + log1pf(expf(-fabsf(z)));

        // Rotate buffers (register moves; cheap vs. the saved latency).
        c0 = n0; c1 = n1; c2 = n2; c3 = n3;
    }

    if (lane == 0) s_warp[warp] = nll;
    __syncthreads();

    if (threadIdx.x == 0) {
        float bs = 0.0f;
        #pragma unroll
        for (int i = 0; i < WPB; ++i) bs += s_warp[i];
        g_partials[blockIdx.x] = bs;
    }
    __threadfence();

    // Last-block-done: one block deterministically reduces all partials.
    __shared__ unsigned int s_last;
    if (threadIdx.x == 0)
        s_last = (atomicAdd(&g_count, 1u) == (unsigned)(gridDim.x - 1));
    __syncthreads();

    if (s_last) {
        float s = 0.0f;
        #pragma unroll
        for (int i = 0; i < NBLOCK / 128; ++i)
            s += g_partials[threadIdx.x + i * 128];

        __shared__ float sm[128];
        sm[threadIdx.x] = s;
        __syncthreads();
        #pragma unroll
        for (int k = 64; k > 0; k >>= 1) {
            if (threadIdx.x < k) sm[threadIdx.x] += sm[threadIdx.x + k];
            __syncthreads();
        }
        if (threadIdx.x == 0) {
            out[0]  = sm[0] * (1.0f / (float)NTOK);
            g_count = 0;   // reset for next launch / graph replay
        }
    }
}

extern "C" void kernel_launch(void* const* d_in, const int* in_sizes, int n_in,
                              void* d_out, int out_size)
{
    const float* hidden     = (const float*)d_in[0];
    const float* node_emb   = (const float*)d_in[1];
    const float* path_signs = (const float*)d_in[2];
    const int*   targets    = (const int*)  d_in[3];
    const int*   path_nodes = (const int*)  d_in[4];
    const int*   path_lens  = (const int*)  d_in[5];
    float*       out        = (float*)d_out;

    hs_kernel<<<NBLOCK, 128>>>(hidden, node_emb, path_signs,
                               targets, path_nodes, path_lens, out);
}

// round 13
// speedup vs baseline: 1.2282x; 1.0848x over previous
#include <cuda_runtime.h>
#include <cuda_pipeline.h>
#include <math.h>

#define VOCAB   50257
#define DIM     512
#define MAXDEP  20
#define NTOK    8192            // B*S
#define WPB     4               // warps (tokens) per 128-thread block
#define NBLOCK  (NTOK / WPB)    // 2048 blocks
#define PSTAGE  3               // pipeline depth (rows in flight per warp)

__device__ float        g_partials[NBLOCK];
__device__ unsigned int g_count = 0;   // self-resets -> graph-replay safe

__global__ void __launch_bounds__(128) hs_kernel(
    const float* __restrict__ hidden,      // [NTOK, DIM]
    const float* __restrict__ node_emb,    // [VOCAB-1, DIM]
    const float* __restrict__ path_signs,  // [VOCAB, MAXDEP]
    const int*   __restrict__ targets,     // [NTOK]
    const int*   __restrict__ path_nodes,  // [VOCAB, MAXDEP]
    const int*   __restrict__ path_lens,   // [VOCAB]
    float*       __restrict__ out)
{
    __shared__ __align__(16) float s_rows[WPB][PSTAGE][DIM];   // 24 KB
    __shared__ float s_warp[WPB];

    const int warp = threadIdx.x >> 5;
    const int lane = threadIdx.x & 31;
    const int tok  = blockIdx.x * WPB + warp;

    const int t   = targets[tok];
    int       len = path_lens[t];
    if (len < 1) len = 1;

    // Coalesced preload of path metadata; broadcast via shfl at use sites.
    int   my_node = 0;
    float my_sign = 1.0f;
    if (lane < MAXDEP) {
        my_node = path_nodes[(size_t)t * MAXDEP + lane];
        my_sign = (path_signs[(size_t)t * MAXDEP + lane] >= 0.0f) ? 1.0f : -1.0f;
    }

    // Hidden row: 16 floats/lane in registers.
    const float4* h4 = reinterpret_cast<const float4*>(hidden + (size_t)tok * DIM);
    const float4 h0 = h4[lane];
    const float4 h1 = h4[lane + 32];
    const float4 h2 = h4[lane + 64];
    const float4 h3 = h4[lane + 96];

    // ---- Prologue: async-stage rows 0..PSTAGE-1 into this warp's smem ring.
    //      One commit per stage; empty commits past len keep counts balanced.
    #pragma unroll
    for (int k = 0; k < PSTAGE; ++k) {
        if (k < len) {   // warp-uniform
            const int node = __shfl_sync(0xffffffffu, my_node, k);
            const float4* g =
                reinterpret_cast<const float4*>(node_emb + (size_t)node * DIM);
            float4* s = reinterpret_cast<float4*>(&s_rows[warp][k][0]);
            #pragma unroll
            for (int j = 0; j < 4; ++j)
                __pipeline_memcpy_async(&s[lane + 32 * j], &g[lane + 32 * j], 16);
        }
        __pipeline_commit();
    }

    float nll  = 0.0f;
    int   slot = 0;

    for (int d = 0; d < len; ++d) {
        // Row d's group is complete when <= PSTAGE-1 groups remain pending.
        __pipeline_wait_prior(PSTAGE - 1);
        __syncwarp();

        // Each lane reads back exactly the 4 float4s it copied.
        const float4* w4 = reinterpret_cast<const float4*>(&s_rows[warp][slot][0]);
        const float4 w0 = w4[lane];
        const float4 w1 = w4[lane + 32];
        const float4 w2 = w4[lane + 64];
        const float4 w3 = w4[lane + 96];

        // Refill this slot for row d+PSTAGE (async write lands far after the LDS).
        if (d + PSTAGE < len) {   // warp-uniform
            const int node = __shfl_sync(0xffffffffu, my_node, d + PSTAGE);
            const float4* g =
                reinterpret_cast<const float4*>(node_emb + (size_t)node * DIM);
            float4* s = reinterpret_cast<float4*>(&s_rows[warp][slot][0]);
            #pragma unroll
            for (int j = 0; j < 4; ++j)
                __pipeline_memcpy_async(&s[lane + 32 * j], &g[lane + 32 * j], 16);
        }
        __pipeline_commit();

        // Dot product partial + warp butterfly.
        float a;
        a = h0.x * w0.x;           a = fmaf(h0.y, w0.y, a);
        a = fmaf(h0.z, w0.z, a);   a = fmaf(h0.w, w0.w, a);
        a = fmaf(h1.x, w1.x, a);   a = fmaf(h1.y, w1.y, a);
        a = fmaf(h1.z, w1.z, a);   a = fmaf(h1.w, w1.w, a);
        a = fmaf(h2.x, w2.x, a);   a = fmaf(h2.y, w2.y, a);
        a = fmaf(h2.z, w2.z, a);   a = fmaf(h2.w, w2.w, a);
        a = fmaf(h3.x, w3.x, a);   a = fmaf(h3.y, w3.y, a);
        a = fmaf(h3.z, w3.z, a);   a = fmaf(h3.w, w3.w, a);

        #pragma unroll
        for (int off = 16; off > 0; off >>= 1)
            a += __shfl_xor_sync(0xffffffffu, a, off);

        const float sgn = __shfl_sync(0xffffffffu, my_sign, d);
        const float z   = sgn * a;
        // -log sigmoid(z) = max(-z,0) + log1p(exp(-|z|))   (stable)
        nll += fmaxf(-z, 0.0f) + log1pf(expf(-fabsf(z)));

        if (++slot == PSTAGE) slot = 0;
    }

    __pipeline_wait_prior(0);   // drain before smem reuse / exit

    if (lane == 0) s_warp[warp] = nll;
    __syncthreads();

    if (threadIdx.x == 0) {
        float bs = 0.0f;
        #pragma unroll
        for (int i = 0; i < WPB; ++i) bs += s_warp[i];
        g_partials[blockIdx.x] = bs;
    }
    __threadfence();

    // Last-block-done: one block deterministically reduces all partials.
    __shared__ unsigned int s_last;
    if (threadIdx.x == 0)
        s_last = (atomicAdd(&g_count, 1u) == (unsigned)(gridDim.x - 1));
    __syncthreads();

    if (s_last) {
        float s = 0.0f;
        #pragma unroll
        for (int i = 0; i < NBLOCK / 128; ++i)
            s += g_partials[threadIdx.x + i * 128];

        __shared__ float sm[128];
        sm[threadIdx.x] = s;
        __syncthreads();
        #pragma unroll
        for (int k = 64; k > 0; k >>= 1) {
            if (threadIdx.x < k) sm[threadIdx.x] += sm[threadIdx.x + k];
            __syncthreads();
        }
        if (threadIdx.x == 0) {
            out[0]  = sm[0] * (1.0f / (float)NTOK);
            g_count = 0;   // reset for next launch / graph replay
        }
    }
}

extern "C" void kernel_launch(void* const* d_in, const int* in_sizes, int n_in,
                              void* d_out, int out_size)
{
    const float* hidden     = (const float*)d_in[0];
    const float* node_emb   = (const float*)d_in[1];
    const float* path_signs = (const float*)d_in[2];
    const int*   targets    = (const int*)  d_in[3];
    const int*   path_nodes = (const int*)  d_in[4];
    const int*   path_lens  = (const int*)  d_in[5];
    float*       out        = (float*)d_out;

    hs_kernel<<<NBLOCK, 128>>>(hidden, node_emb, path_signs,
                               targets, path_nodes, path_lens, out);
}

// round 15
// speedup vs baseline: 1.2356x; 1.0060x over previous
#include <cuda_runtime.h>
#include <cuda_pipeline.h>
#include <math.h>

#define VOCAB   50257
#define DIM     512
#define MAXDEP  20
#define NTOK    8192            // B*S; one single-warp CTA per token
#define PSTAGE  3               // pipeline depth (rows in flight per warp)

__device__ float        g_partials[NTOK];
__device__ unsigned int g_count = 0;   // self-resets -> graph-replay safe

__global__ void __launch_bounds__(32) hs_kernel(
    const float* __restrict__ hidden,      // [NTOK, DIM]
    const float* __restrict__ node_emb,    // [VOCAB-1, DIM]
    const float* __restrict__ path_signs,  // [VOCAB, MAXDEP]
    const int*   __restrict__ targets,     // [NTOK]
    const int*   __restrict__ path_nodes,  // [VOCAB, MAXDEP]
    const int*   __restrict__ path_lens,   // [VOCAB]
    float*       __restrict__ out)
{
    __shared__ __align__(16) float s_rows[PSTAGE][DIM];   // 6 KB

    const int lane = threadIdx.x;          // 32-thread CTA = one warp
    const int tok  = blockIdx.x;

    const int t   = targets[tok];
    int       len = path_lens[t];
    if (len < 1) len = 1;

    // Coalesced preload of path metadata; broadcast via shfl at use sites.
    int   my_node = 0;
    float my_sign = 1.0f;
    if (lane < MAXDEP) {
        my_node = path_nodes[(size_t)t * MAXDEP + lane];
        my_sign = (path_signs[(size_t)t * MAXDEP + lane] >= 0.0f) ? 1.0f : -1.0f;
    }

    // Hidden row: 16 floats/lane in registers.
    const float4* h4 = reinterpret_cast<const float4*>(hidden + (size_t)tok * DIM);
    const float4 h0 = h4[lane];
    const float4 h1 = h4[lane + 32];
    const float4 h2 = h4[lane + 64];
    const float4 h3 = h4[lane + 96];

    // ---- Prologue: async-stage rows 0..PSTAGE-1 into the smem ring.
    //      One commit per stage; empty commits past len keep counts balanced.
    #pragma unroll
    for (int k = 0; k < PSTAGE; ++k) {
        if (k < len) {   // warp-uniform
            const int node = __shfl_sync(0xffffffffu, my_node, k);
            const float4* g =
                reinterpret_cast<const float4*>(node_emb + (size_t)node * DIM);
            float4* s = reinterpret_cast<float4*>(&s_rows[k][0]);
            #pragma unroll
            for (int j = 0; j < 4; ++j)
                __pipeline_memcpy_async(&s[lane + 32 * j], &g[lane + 32 * j], 16);
        }
        __pipeline_commit();
    }

    float nll  = 0.0f;
    int   slot = 0;

    for (int d = 0; d < len; ++d) {
        // Row d's group complete when <= PSTAGE-1 groups remain pending.
        __pipeline_wait_prior(PSTAGE - 1);
        __syncwarp();

        // Each lane reads back exactly the 4 float4s it copied.
        const float4* w4 = reinterpret_cast<const float4*>(&s_rows[slot][0]);
        const float4 w0 = w4[lane];
        const float4 w1 = w4[lane + 32];
        const float4 w2 = w4[lane + 64];
        const float4 w3 = w4[lane + 96];

        // Refill this slot for row d+PSTAGE (async write lands far after the LDS).
        if (d + PSTAGE < len) {   // warp-uniform
            const int node = __shfl_sync(0xffffffffu, my_node, d + PSTAGE);
            const float4* g =
                reinterpret_cast<const float4*>(node_emb + (size_t)node * DIM);
            float4* s = reinterpret_cast<float4*>(&s_rows[slot][0]);
            #pragma unroll
            for (int j = 0; j < 4; ++j)
                __pipeline_memcpy_async(&s[lane + 32 * j], &g[lane + 32 * j], 16);
        }
        __pipeline_commit();

        // Dot product partial + warp butterfly.
        float a;
        a = h0.x * w0.x;           a = fmaf(h0.y, w0.y, a);
        a = fmaf(h0.z, w0.z, a);   a = fmaf(h0.w, w0.w, a);
        a = fmaf(h1.x, w1.x, a);   a = fmaf(h1.y, w1.y, a);
        a = fmaf(h1.z, w1.z, a);   a = fmaf(h1.w, w1.w, a);
        a = fmaf(h2.x, w2.x, a);   a = fmaf(h2.y, w2.y, a);
        a = fmaf(h2.z, w2.z, a);   a = fmaf(h2.w, w2.w, a);
        a = fmaf(h3.x, w3.x, a);   a = fmaf(h3.y, w3.y, a);
        a = fmaf(h3.z, w3.z, a);   a = fmaf(h3.w, w3.w, a);

        #pragma unroll
        for (int off = 16; off > 0; off >>= 1)
            a += __shfl_xor_sync(0xffffffffu, a, off);

        const float sgn = __shfl_sync(0xffffffffu, my_sign, d);
        const float z   = sgn * a;
        // -log sigmoid(z) = max(-z,0) + log1p(exp(-|z|))   (stable)
        nll += fmaxf(-z, 0.0f) + log1pf(expf(-fabsf(z)));

        if (++slot == PSTAGE) slot = 0;
    }

    __pipeline_wait_prior(0);   // drain before exit

    if (lane == 0) g_partials[tok] = nll;
    __threadfence();

    // Last-block-done: one warp deterministically reduces all 8192 partials.
    __shared__ unsigned int s_last;
    if (lane == 0)
        s_last = (atomicAdd(&g_count, 1u) == (unsigned)(gridDim.x - 1));
    __syncwarp();
    const unsigned last = __shfl_sync(0xffffffffu, s_last, 0);

    if (last) {
        // 32 lanes x 64 float4 = 8192 floats; independent loads -> high MLP.
        const float4* p4 = reinterpret_cast<const float4*>(g_partials);
        float s = 0.0f;
        #pragma unroll
        for (int i = 0; i < NTOK / (32 * 4); ++i) {
            const float4 v = p4[lane + 32 * i];
            s += (v.x + v.y) + (v.z + v.w);
        }
        #pragma unroll
        for (int off = 16; off > 0; off >>= 1)
            s += __shfl_xor_sync(0xffffffffu, s, off);
        if (lane == 0) {
            out[0]  = s * (1.0f / (float)NTOK);
            g_count = 0;   // reset for next launch / graph replay
        }
    }
}

extern "C" void kernel_launch(void* const* d_in, const int* in_sizes, int n_in,
                              void* d_out, int out_size)
{
    const float* hidden     = (const float*)d_in[0];
    const float* node_emb   = (const float*)d_in[1];
    const float* path_signs = (const float*)d_in[2];
    const int*   targets    = (const int*)  d_in[3];
    const int*   path_nodes = (const int*)  d_in[4];
    const int*   path_lens  = (const int*)  d_in[5];
    float*       out        = (float*)d_out;

    hs_kernel<<<NTOK, 32>>>(hidden, node_emb, path_signs,
                            targets, path_nodes, path_lens, out);
}